// round 5
// baseline (speedup 1.0000x reference)
#include <cuda_runtime.h>
#include <cuda_bf16.h>
#include <cstdint>
#include <math.h>

// Problem constants
#define O_NODES 10000
#define T_EDGES 50000
#define HH      512
#define NG      2048
#define N2      1152
#define HIST_SZ 131072

// ---------------- scratch (__device__ globals) --------------------------------
__device__ float g_mid [(size_t)T_EDGES * HH];
__device__ float g_newt[(size_t)T_EDGES * N2];
__device__ float g_gxs [(size_t)T_EDGES * NG];
__device__ float g_gxo [(size_t)T_EDGES * NG];
__device__ float g_G   [(size_t)O_NODES * NG];
__device__ float g_hs  [(size_t)O_NODES * HH];
__device__ float g_cs  [(size_t)O_NODES * HH];
__device__ float g_prev[(size_t)O_NODES * HH];
// bf16 hi/lo operand buffers ([rows][2K]: hi cols 0..K-1, lo cols K..2K-1)
__device__ __nv_bfloat16 g_curhl [(size_t)T_EDGES * 768];
__device__ __nv_bfloat16 g_midhl [(size_t)T_EDGES * 1024];
__device__ __nv_bfloat16 g_shl   [(size_t)T_EDGES * 1024];
__device__ __nv_bfloat16 g_ohl   [(size_t)T_EDGES * 1024];
__device__ __nv_bfloat16 g_objhl [(size_t)O_NODES * 256];
__device__ __nv_bfloat16 g_hshl  [(size_t)O_NODES * 1024];
__device__ __nv_bfloat16 g_pchl  [(size_t)O_NODES * 2048];
// weights hi/lo
__device__ __nv_bfloat16 g_w1hl   [512  * 768];
__device__ __nv_bfloat16 g_w2hl   [1152 * 1024];
__device__ __nv_bfloat16 g_wihhl  [2048 * 1024];
__device__ __nv_bfloat16 g_whhhl  [2048 * 1024];
__device__ __nv_bfloat16 g_wprojhl[512  * 256];
__device__ __nv_bfloat16 g_wouthl [128  * 2048];
// sort scratch
__device__ int g_hist[HIST_SZ];
__device__ int g_cursor[HIST_SZ];
__device__ int g_cnt[HIST_SZ];
__device__ int g_order[O_NODES];
__device__ int g_pos[O_NODES];

// ---------------- PTX helpers --------------------------------------------------
__device__ __forceinline__ void cpa16(uint32_t sdst, const void* gsrc, int src_bytes) {
    asm volatile("cp.async.cg.shared.global [%0], [%1], 16, %2;\n"
                 :: "r"(sdst), "l"(gsrc), "r"(src_bytes) : "memory");
}
__device__ __forceinline__ void cpa_commit() {
    asm volatile("cp.async.commit_group;\n" ::: "memory");
}
template<int N>
__device__ __forceinline__ void cpa_wait() {
    asm volatile("cp.async.wait_group %0;\n" :: "n"(N) : "memory");
}

__device__ __forceinline__ void ldm4(unsigned* r, uint32_t addr) {
    asm volatile("ldmatrix.sync.aligned.m8n8.x4.shared.b16 {%0,%1,%2,%3}, [%4];"
                 : "=r"(r[0]), "=r"(r[1]), "=r"(r[2]), "=r"(r[3]) : "r"(addr));
}

__device__ __forceinline__ void mma_bf16(float* d, const unsigned* a, const unsigned* b) {
    asm volatile(
        "mma.sync.aligned.m16n8k16.row.col.f32.bf16.bf16.f32 "
        "{%0,%1,%2,%3}, {%4,%5,%6,%7}, {%8,%9}, {%0,%1,%2,%3};\n"
        : "+f"(d[0]), "+f"(d[1]), "+f"(d[2]), "+f"(d[3])
        : "r"(a[0]), "r"(a[1]), "r"(a[2]), "r"(a[3]), "r"(b[0]), "r"(b[1]));
}

// ---------------- split-bf16 mma.sync GEMM -------------------------------------
// C[M,N] = act(A[M,K] @ B[N,K]^T + bias) as Ahi.Bhi + Ahi.Blo + Alo.Bhi.
// A,B are bf16 hi/lo arrays [rows][2K]. Tile 128x128, BK=32 bf16 per stage,
// 8 warps x (64x32), ldmatrix.x4 frags, double-buffered cp.async.
// smem pitch 40 bf16 (80B = 5*16B, odd multiple -> ldmatrix conflict-free).

template<bool RELU, bool BIAS>
__global__ void __launch_bounds__(256)
bgemm(const __nv_bfloat16* __restrict__ A,
      const __nv_bfloat16* __restrict__ B,
      int K,
      const float* __restrict__ bias,
      float* __restrict__ C, int ldc,
      int M, const int* __restrict__ mdev)
{
    if (mdev) M = *mdev;
    const int m0 = blockIdx.y * 128;
    if (m0 >= M) return;
    const int n0 = blockIdx.x * 128;

    __shared__ __nv_bfloat16 As[2][128][40];
    __shared__ __nv_bfloat16 Bs[2][128][40];

    const int tid  = threadIdx.x;
    const int warp = tid >> 5, lane = tid & 31;
    const int wm = (warp & 1) * 64;
    const int wn = (warp >> 1) * 32;

    const uint32_t saA = (uint32_t)__cvta_generic_to_shared(&As[0][0][0]);
    const uint32_t saB = (uint32_t)__cvta_generic_to_shared(&Bs[0][0][0]);
    const uint32_t BUF = 128u * 40u * 2u;   // 10240 B per buffer

    const size_t lda = (size_t)(2 * K);
    const int J = K >> 5;      // 32-wide slabs per phase
    const int S = 3 * J;

    // loader: A/B tiles 128 rows x 32 bf16 (64B/row); 4 threads/row, 2 row-passes
    const int lrow = tid >> 2;
    const int lc16 = tid & 3;

    auto load_slab = [&](int s, int buf) {
        int p = s / J, j = s - p * J;
        int aoff = ((p == 2) ? K : 0) + j * 32;
        int boff = ((p == 1) ? K : 0) + j * 32;
#pragma unroll
        for (int i = 0; i < 2; i++) {
            int row = lrow + i * 64;
            uint32_t soff = (uint32_t)buf * BUF + (uint32_t)(row * 80 + lc16 * 16);
            const __nv_bfloat16* ga = A + (size_t)(m0 + row) * lda + aoff + lc16 * 8;
            cpa16(saA + soff, ga, ((m0 + row) < M) ? 16 : 0);
            const __nv_bfloat16* gb = B + (size_t)(n0 + row) * lda + boff + lc16 * 8;
            cpa16(saB + soff, gb, 16);
        }
        cpa_commit();
    };

    float acc[4][4][4];
#pragma unroll
    for (int i = 0; i < 4; i++)
#pragma unroll
        for (int j = 0; j < 4; j++)
#pragma unroll
            for (int q = 0; q < 4; q++) acc[i][j][q] = 0.f;

    load_slab(0, 0);

    for (int s = 0; s < S; ++s) {
        if (s + 1 < S) { load_slab(s + 1, (s + 1) & 1); cpa_wait<1>(); }
        else           { cpa_wait<0>(); }
        __syncthreads();

        const uint32_t buf = (uint32_t)(s & 1) * BUF;
#pragma unroll
        for (int kt = 0; kt < 2; kt++) {
            unsigned a[4][4], b[2][4];
#pragma unroll
            for (int mt = 0; mt < 4; mt++) {
                uint32_t addr = saA + buf
                    + (uint32_t)((wm + mt * 16 + (lane & 15)) * 80)
                    + (uint32_t)(kt * 32 + ((lane >> 4) & 1) * 16);
                ldm4(a[mt], addr);
            }
#pragma unroll
            for (int np = 0; np < 2; np++) {
                int row = wn + np * 16 + (lane & 7) + ((lane >> 4) & 1) * 8;
                uint32_t addr = saB + buf + (uint32_t)(row * 80)
                    + (uint32_t)(kt * 32 + ((lane >> 3) & 1) * 16);
                ldm4(b[np], addr);
            }
#pragma unroll
            for (int mt = 0; mt < 4; mt++)
#pragma unroll
                for (int nf = 0; nf < 4; nf++)
                    mma_bf16(acc[mt][nf], a[mt], &b[nf >> 1][(nf & 1) * 2]);
        }
        __syncthreads();
    }

    // epilogue: m16n8 C frag -> lane l owns rows (l/4, l/4+8), cols 2*(l%4)+{0,1}
    const int r = lane >> 2, cc2 = (lane & 3) * 2;
#pragma unroll
    for (int mt = 0; mt < 4; mt++) {
        int row0 = m0 + wm + mt * 16 + r;
#pragma unroll
        for (int nf = 0; nf < 4; nf++) {
            int col = n0 + wn + nf * 8 + cc2;
            float bx = 0.f, by = 0.f;
            if (BIAS) { bx = bias[col]; by = bias[col + 1]; }
            if (row0 < M) {
                float vx = acc[mt][nf][0] + bx;
                float vy = acc[mt][nf][1] + by;
                if (RELU) { vx = fmaxf(vx, 0.f); vy = fmaxf(vy, 0.f); }
                *(float2*)(C + (size_t)row0 * ldc + col) = make_float2(vx, vy);
            }
            if (row0 + 8 < M) {
                float vx = acc[mt][nf][2] + bx;
                float vy = acc[mt][nf][3] + by;
                if (RELU) { vx = fmaxf(vx, 0.f); vy = fmaxf(vy, 0.f); }
                *(float2*)(C + (size_t)(row0 + 8) * ldc + col) = make_float2(vx, vy);
            }
        }
    }
}

// ---------------- conversions & pointwise --------------------------------------
__device__ __forceinline__ void hilo(float x, __nv_bfloat16& h, __nv_bfloat16& l) {
    h = __float2bfloat16(x);
    l = __float2bfloat16(x - __bfloat162float(h));
}

__global__ void k_cvt(const float* __restrict__ src, int src_ld,
                      __nv_bfloat16* __restrict__ dst, int Kc, int total)
{
    int i = blockIdx.x * blockDim.x + threadIdx.x;
    if (i >= total) return;
    int r = i / Kc, c = i - r * Kc;
    __nv_bfloat16 h, l;
    hilo(src[(size_t)r * src_ld + c], h, l);
    dst[(size_t)r * 2 * Kc + c] = h;
    dst[(size_t)r * 2 * Kc + Kc + c] = l;
}

__global__ void k_zero_hist()
{
    int i = blockIdx.x * blockDim.x + threadIdx.x;
    if (i < HIST_SZ) g_hist[i] = 0;
}

__global__ void k_init_hc()
{
    int i = blockIdx.x * blockDim.x + threadIdx.x;
    if (i < O_NODES * HH / 4) {
        ((float4*)g_hs)[i] = make_float4(0.f, 0.f, 0.f, 0.f);
        ((float4*)g_cs)[i] = make_float4(0.f, 0.f, 0.f, 0.f);
        ((uint4*)g_hshl)[i] = make_uint4(0, 0, 0, 0);
    }
}

__global__ void k_hist(const int* __restrict__ lengths)
{
    int n = blockIdx.x * blockDim.x + threadIdx.x;
    if (n < O_NODES) atomicAdd(&g_hist[lengths[n]], 1);
}

__global__ void k_scan(int L)
{
    int run = 0;
    for (int len = L; len >= 0; --len) {
        g_cursor[len] = run;
        g_cnt[len]    = run;
        run += g_hist[len];
    }
}

__global__ void k_scatter(const int* __restrict__ lengths)
{
    int n = blockIdx.x * blockDim.x + threadIdx.x;
    if (n >= O_NODES) return;
    int pos = atomicAdd(&g_cursor[lengths[n]], 1);
    g_order[pos] = n;
    g_pos[n] = pos;
}

__global__ void k_build_curhl(const float* __restrict__ obj,
                              const float* __restrict__ pred,
                              const int* __restrict__ edges)
{
    int i = blockIdx.x * blockDim.x + threadIdx.x;
    if (i >= T_EDGES * 384) return;
    int e = i / 384, q = i - e * 384;
    float v;
    if (q < 128)       v = obj[(size_t)edges[2 * e] * 128 + q];
    else if (q < 256)  v = pred[(size_t)e * 128 + (q - 128)];
    else               v = obj[(size_t)edges[2 * e + 1] * 128 + (q - 256)];
    __nv_bfloat16 h, l;
    hilo(v, h, l);
    g_curhl[(size_t)e * 768 + q] = h;
    g_curhl[(size_t)e * 768 + 384 + q] = l;
}

__global__ void k_copy_newp(float* __restrict__ out)
{
    int i = blockIdx.x * blockDim.x + threadIdx.x;
    if (i >= T_EDGES * 32) return;
    int e = i / 32, q = i - e * 32;
    ((float4*)out)[(size_t)(O_NODES * 32) + (size_t)e * 32 + q] =
        ((const float4*)g_newt)[(size_t)e * 288 + 128 + q];
}

__device__ __forceinline__ float sigm(float x) { return 1.f / (1.f + expf(-x)); }

__global__ void k_lstm_update(int t, int L,
                              const int* __restrict__ nbr,
                              const float* __restrict__ bih,
                              const float* __restrict__ bhh)
{
    int row = blockIdx.x;
    if (row >= g_cnt[t]) return;
    int j = threadIdx.x;
    int node = g_order[row];
    int idx  = nbr[(size_t)node * L + t];

    const float* Gr = g_G + (size_t)row * NG;
    float gi = Gr[j], gf = Gr[512 + j], gg = Gr[1024 + j], go = Gr[1536 + j];

    if (idx > 0) {
        const float* gx = (idx <= T_EDGES)
            ? g_gxs + (size_t)(idx - 1) * NG
            : g_gxo + (size_t)(idx - 1 - T_EDGES) * NG;
        gi += gx[j]; gf += gx[512 + j]; gg += gx[1024 + j]; go += gx[1536 + j];
    }
    gi += bih[j]        + bhh[j];
    gf += bih[512 + j]  + bhh[512 + j];
    gg += bih[1024 + j] + bhh[1024 + j];
    go += bih[1536 + j] + bhh[1536 + j];

    float cc = g_cs[(size_t)row * HH + j];
    float c2 = sigm(gf) * cc + sigm(gi) * tanhf(gg);
    float h2 = sigm(go) * tanhf(c2);
    g_cs[(size_t)row * HH + j] = c2;
    g_hs[(size_t)row * HH + j] = h2;
    __nv_bfloat16 h, l;
    hilo(h2, h, l);
    g_hshl[(size_t)row * 1024 + j] = h;
    g_hshl[(size_t)row * 1024 + 512 + j] = l;
}

__global__ void k_build_pchl()
{
    int i = blockIdx.x * blockDim.x + threadIdx.x;
    if (i >= O_NODES * 1024) return;
    int n = i >> 10, q = i & 1023;
    float v = (q < 512) ? g_hs[(size_t)g_pos[n] * HH + q]
                        : g_prev[(size_t)n * HH + (q - 512)];
    __nv_bfloat16 h, l;
    hilo(v, h, l);
    g_pchl[(size_t)n * 2048 + q] = h;
    g_pchl[(size_t)n * 2048 + 1024 + q] = l;
}

// ---------------- launcher -----------------------------------------------------
extern "C" void kernel_launch(void* const* d_in, const int* in_sizes, int n_in,
                              void* d_out, int out_size)
{
    const float* obj    = (const float*)d_in[0];
    const float* pred   = (const float*)d_in[1];
    const int*   edges  = (const int*)  d_in[2];
    const int*   nbr    = (const int*)  d_in[3];
    const int*   lengths= (const int*)  d_in[4];
    const float* W1     = (const float*)d_in[5];
    const float* b1     = (const float*)d_in[6];
    const float* W2     = (const float*)d_in[7];
    const float* b2     = (const float*)d_in[8];
    const float* Wih    = (const float*)d_in[9];
    const float* Whh    = (const float*)d_in[10];
    const float* bih    = (const float*)d_in[11];
    const float* bhh    = (const float*)d_in[12];
    const float* Wproj  = (const float*)d_in[13];
    const float* bproj  = (const float*)d_in[14];
    const float* Wout   = (const float*)d_in[15];
    const float* bout   = (const float*)d_in[16];
    float* out = (float*)d_out;

    const int L = in_sizes[3] / O_NODES;

    float *p_mid, *p_newt, *p_gxs, *p_gxo, *p_G, *p_hs, *p_prev;
    __nv_bfloat16 *p_curhl, *p_midhl, *p_shl, *p_ohl, *p_objhl, *p_hshl, *p_pchl;
    __nv_bfloat16 *p_w1, *p_w2, *p_wih, *p_whh, *p_wproj, *p_wout;
    int *p_cnt;
    cudaGetSymbolAddress((void**)&p_mid,   g_mid);
    cudaGetSymbolAddress((void**)&p_newt,  g_newt);
    cudaGetSymbolAddress((void**)&p_gxs,   g_gxs);
    cudaGetSymbolAddress((void**)&p_gxo,   g_gxo);
    cudaGetSymbolAddress((void**)&p_G,     g_G);
    cudaGetSymbolAddress((void**)&p_hs,    g_hs);
    cudaGetSymbolAddress((void**)&p_prev,  g_prev);
    cudaGetSymbolAddress((void**)&p_curhl, g_curhl);
    cudaGetSymbolAddress((void**)&p_midhl, g_midhl);
    cudaGetSymbolAddress((void**)&p_shl,   g_shl);
    cudaGetSymbolAddress((void**)&p_ohl,   g_ohl);
    cudaGetSymbolAddress((void**)&p_objhl, g_objhl);
    cudaGetSymbolAddress((void**)&p_hshl,  g_hshl);
    cudaGetSymbolAddress((void**)&p_pchl,  g_pchl);
    cudaGetSymbolAddress((void**)&p_w1,    g_w1hl);
    cudaGetSymbolAddress((void**)&p_w2,    g_w2hl);
    cudaGetSymbolAddress((void**)&p_wih,   g_wihhl);
    cudaGetSymbolAddress((void**)&p_whh,   g_whhhl);
    cudaGetSymbolAddress((void**)&p_wproj, g_wprojhl);
    cudaGetSymbolAddress((void**)&p_wout,  g_wouthl);
    cudaGetSymbolAddress((void**)&p_cnt,   g_cnt);

    const int MT_E = (T_EDGES + 127) / 128;   // 391
    const int MT_O = (O_NODES + 127) / 128;   // 79

    // weight conversions (fp32 -> bf16 hi/lo)
    k_cvt<<<(512 * 384 + 255) / 256, 256>>>(W1, 384, p_w1, 384, 512 * 384);
    k_cvt<<<(1152 * 512 + 255) / 256, 256>>>(W2, 512, p_w2, 512, 1152 * 512);
    k_cvt<<<(2048 * 512 + 255) / 256, 256>>>(Wih, 512, p_wih, 512, 2048 * 512);
    k_cvt<<<(2048 * 512 + 255) / 256, 256>>>(Whh, 512, p_whh, 512, 2048 * 512);
    k_cvt<<<(512 * 128 + 255) / 256, 256>>>(Wproj, 128, p_wproj, 128, 512 * 128);
    k_cvt<<<(128 * 1024 + 255) / 256, 256>>>(Wout, 1024, p_wout, 1024, 128 * 1024);
    k_cvt<<<(O_NODES * 128 + 255) / 256, 256>>>(obj, 128, p_objhl, 128, O_NODES * 128);

    // node sort by length (descending) + state init
    k_zero_hist<<<HIST_SZ / 256, 256>>>();
    k_init_hc<<<(O_NODES * HH / 4 + 255) / 256, 256>>>();
    k_hist<<<(O_NODES + 255) / 256, 256>>>(lengths);
    k_scan<<<1, 1>>>(L);
    k_scatter<<<(O_NODES + 255) / 256, 256>>>(lengths);

    // edge MLP
    k_build_curhl<<<(T_EDGES * 384 + 255) / 256, 256>>>(obj, pred, edges);
    bgemm<true,  true ><<<dim3(4, MT_E), 256>>>(p_curhl, p_w1, 384, b1, p_mid, 512, T_EDGES, nullptr);
    k_cvt<<<(T_EDGES * 512 + 255) / 256, 256>>>(p_mid, 512, p_midhl, 512, T_EDGES * 512);
    bgemm<true,  true ><<<dim3(9, MT_E), 256>>>(p_midhl, p_w2, 512, b2, p_newt, N2, T_EDGES, nullptr);
    k_copy_newp<<<(T_EDGES * 32 + 255) / 256, 256>>>(out);
    k_cvt<<<(T_EDGES * 512 + 255) / 256, 256>>>(p_newt,       N2, p_shl, 512, T_EDGES * 512);
    k_cvt<<<(T_EDGES * 512 + 255) / 256, 256>>>(p_newt + 640, N2, p_ohl, 512, T_EDGES * 512);

    // LSTM input-gate precompute
    bgemm<false, false><<<dim3(16, MT_E), 256>>>(p_shl, p_wih, 512, nullptr, p_gxs, NG, T_EDGES, nullptr);
    bgemm<false, false><<<dim3(16, MT_E), 256>>>(p_ohl, p_wih, 512, nullptr, p_gxo, NG, T_EDGES, nullptr);

    // prev = obj @ Wproj^T + bproj
    bgemm<false, true ><<<dim3(4, MT_O), 256>>>(p_objhl, p_wproj, 128, bproj, p_prev, 512, O_NODES, nullptr);

    // LSTM recurrence
    for (int t = 0; t < L; ++t) {
        bgemm<false, false><<<dim3(16, MT_O), 256>>>(p_hshl, p_whh, 512, nullptr, p_G, NG, O_NODES, p_cnt + t);
        k_lstm_update<<<O_NODES, 512>>>(t, L, nbr, bih, bhh);
    }

    // new_obj = [pooled | prev] @ Wout^T + bout
    k_build_pchl<<<(O_NODES * 1024 + 255) / 256, 256>>>();
    bgemm<false, true ><<<dim3(1, MT_O), 256>>>(p_pchl, p_wout, 1024, bout, out, 128, O_NODES, nullptr);
}

// round 8
// speedup vs baseline: 1.2629x; 1.2629x over previous
#include <cuda_runtime.h>
#include <cstdint>
#include <math.h>

// Problem constants
#define O_NODES 10000
#define T_EDGES 50000
#define HH      512
#define NG      2048
#define HIST_SZ 131072

// ---------------- scratch (__device__ globals) --------------------------------
__device__ float g_cur [(size_t)T_EDGES * 384];
__device__ float g_mid [(size_t)T_EDGES * HH];
__device__ float g_newt[(size_t)T_EDGES * 1152];
__device__ float g_gxs [(size_t)T_EDGES * NG];
__device__ float g_gxo [(size_t)T_EDGES * NG];
__device__ float g_hsA [(size_t)O_NODES * HH];    // h ping-pong buffer 0 (tf32-rounded)
__device__ float g_hsB [(size_t)O_NODES * HH];    // h ping-pong buffer 1
__device__ float g_cs  [(size_t)O_NODES * HH];    // full fp32 c state
__device__ float g_prev[(size_t)O_NODES * HH];
__device__ float g_pc  [(size_t)O_NODES * 1024];
__device__ float g_obj32[(size_t)O_NODES * 128];
// tf32-rounded weights (Wih/Whh rows gate-permuted)
__device__ float g_w1r   [512  * 384];
__device__ float g_w2r   [1152 * 512];
__device__ float g_wihr  [2048 * 512];
__device__ float g_whhr  [2048 * 512];
__device__ float g_wprojr[512  * 128];
__device__ float g_woutr [128  * 1024];
__device__ float g_bias  [2048];                  // permuted bih+bhh
__device__ float g_h1[512];
__device__ float g_c1[512];
// sort scratch
__device__ int g_hist[HIST_SZ];
__device__ int g_cursor[HIST_SZ];
__device__ int g_cnt[HIST_SZ];
__device__ int g_order[O_NODES];
__device__ int g_pos[O_NODES];

// ---------------- helpers ------------------------------------------------------
__device__ __forceinline__ float roundtf(float x) {
    unsigned u;
    asm("cvt.rna.tf32.f32 %0, %1;" : "=r"(u) : "f"(x));
    return __uint_as_float(u);
}
__device__ __forceinline__ float sigm(float x) { return 1.f / (1.f + expf(-x)); }

__device__ __forceinline__ void mma_tf32(float* d, const unsigned* a, const unsigned* b) {
    asm volatile(
        "mma.sync.aligned.m16n8k8.row.col.f32.tf32.tf32.f32 "
        "{%0,%1,%2,%3}, {%4,%5,%6,%7}, {%8,%9}, {%0,%1,%2,%3};\n"
        : "+f"(d[0]), "+f"(d[1]), "+f"(d[2]), "+f"(d[3])
        : "r"(a[0]), "r"(a[1]), "r"(a[2]), "r"(a[3]), "r"(b[0]), "r"(b[1]));
}
__device__ __forceinline__ void cpa16(unsigned sdst, const float* gsrc, int src_bytes) {
    asm volatile("cp.async.cg.shared.global [%0], [%1], 16, %2;\n"
                 :: "r"(sdst), "l"(gsrc), "r"(src_bytes) : "memory");
}
__device__ __forceinline__ void cpa_commit() {
    asm volatile("cp.async.commit_group;\n" ::: "memory");
}
template<int N>
__device__ __forceinline__ void cpa_wait() {
    asm volatile("cp.async.wait_group %0;\n" :: "n"(N) : "memory");
}

// ---------------- tf32 tensor-core GEMM ----------------------------------------
// C[M,N] = epi(A[M,K] @ B[N,K]^T). Inputs pre-rounded to tf32. Tile 128x128,
// BK=16 double-buffered cp.async, 8 warps x (64x32).
// EPI: 0 exact(+bias) | 1 relu+round(+bias) | 2 relu, round except cols[512,640)
//      3 round(+bias) | 4 fused LSTM gate epilogue (writes hout, not C)
template<int EPI, bool BIAS>
__global__ void __launch_bounds__(256, 2)
tgemm(const float* __restrict__ A, int lda,
      const float* __restrict__ B, int K,
      const float* __restrict__ bias,
      float* __restrict__ C, int ldc,
      int M, const int* __restrict__ mdev,
      int t, int L, const int* __restrict__ nbr,
      float* __restrict__ hout)
{
    if (mdev) M = *mdev;
    const int m0 = blockIdx.y * 128;
    if (m0 >= M) return;
    const int n0 = blockIdx.x * 128;

    __shared__ float As[2][128][20];
    __shared__ float Bs[2][128][20];
    float* gbuf = &As[0][0][0];   // EPI==4 epilogue staging (64x132 = 8448 floats)

    const int tid  = threadIdx.x;
    const int warp = tid >> 5, lane = tid & 31;
    const int r = lane >> 2, c = lane & 3;
    const int wm = (warp & 1) * 64;
    const int wn = (warp >> 1) * 32;

    const int lrow = tid >> 1;
    const int lf4  = (tid & 1) * 2;

    const float* Aptr = A + (size_t)(m0 + lrow) * lda + lf4 * 4;
    const float* Bptr = B + (size_t)(n0 + lrow) * K   + lf4 * 4;
    const int abytes = ((m0 + lrow) < M) ? 16 : 0;

    unsigned sa0 = (unsigned)__cvta_generic_to_shared(&As[0][lrow][lf4 * 4]);
    unsigned sb0 = (unsigned)__cvta_generic_to_shared(&Bs[0][lrow][lf4 * 4]);
    const unsigned bufstride = 128 * 20 * 4;

    float acc[4][4][4];
#pragma unroll
    for (int i = 0; i < 4; i++)
#pragma unroll
        for (int j = 0; j < 4; j++)
#pragma unroll
            for (int q = 0; q < 4; q++) acc[i][j][q] = 0.f;

    const int nk = K >> 4;

#pragma unroll
    for (int i = 0; i < 2; i++) {
        cpa16(sa0 + i * 16, Aptr + i * 4, abytes);
        cpa16(sb0 + i * 16, Bptr + i * 4, 16);
    }
    cpa_commit();

    for (int it = 0; it < nk; ++it) {
        if (it + 1 < nk) {
            int nb = (it + 1) & 1;
            int ko = (it + 1) << 4;
#pragma unroll
            for (int i = 0; i < 2; i++) {
                cpa16(sa0 + nb * bufstride + i * 16, Aptr + ko + i * 4, abytes);
                cpa16(sb0 + nb * bufstride + i * 16, Bptr + ko + i * 4, 16);
            }
            cpa_commit();
            cpa_wait<1>();
        } else {
            cpa_wait<0>();
        }
        __syncthreads();

        const int buf = it & 1;
#pragma unroll
        for (int kk = 0; kk < 16; kk += 8) {
            unsigned ua[4][4], ub[4][2];
#pragma unroll
            for (int mt = 0; mt < 4; mt++) {
                int mb = wm + mt * 16 + r;
                ua[mt][0] = __float_as_uint(As[buf][mb    ][kk + c    ]);
                ua[mt][1] = __float_as_uint(As[buf][mb + 8][kk + c    ]);
                ua[mt][2] = __float_as_uint(As[buf][mb    ][kk + c + 4]);
                ua[mt][3] = __float_as_uint(As[buf][mb + 8][kk + c + 4]);
            }
#pragma unroll
            for (int nt = 0; nt < 4; nt++) {
                int nb = wn + nt * 8 + r;
                ub[nt][0] = __float_as_uint(Bs[buf][nb][kk + c    ]);
                ub[nt][1] = __float_as_uint(Bs[buf][nb][kk + c + 4]);
            }
#pragma unroll
            for (int mt = 0; mt < 4; mt++)
#pragma unroll
                for (int nt = 0; nt < 4; nt++)
                    mma_tf32(acc[mt][nt], ua[mt], ub[nt]);
        }
        __syncthreads();
    }

    if (EPI != 4) {
        const int cc2 = c * 2;
#pragma unroll
        for (int mt = 0; mt < 4; mt++) {
            int row0 = m0 + wm + mt * 16 + r;
#pragma unroll
            for (int nt = 0; nt < 4; nt++) {
                int col = n0 + wn + nt * 8 + cc2;
                float bx = 0.f, by = 0.f;
                if (BIAS) { bx = bias[col]; by = bias[col + 1]; }
#pragma unroll
                for (int h = 0; h < 2; h++) {
                    int row = row0 + h * 8;
                    if (row >= M) continue;
                    float vx = acc[mt][nt][h * 2 + 0] + bx;
                    float vy = acc[mt][nt][h * 2 + 1] + by;
                    if (EPI == 1 || EPI == 2) { vx = fmaxf(vx, 0.f); vy = fmaxf(vy, 0.f); }
                    if (EPI == 1 || EPI == 3) { vx = roundtf(vx); vy = roundtf(vy); }
                    if (EPI == 2) {
                        if (col < 512 || col >= 640)     vx = roundtf(vx);
                        if (col + 1 < 512 || col + 1 >= 640) vy = roundtf(vy);
                    }
                    *(float2*)(C + (size_t)row * ldc + col) = make_float2(vx, vy);
                }
            }
        }
    } else {
        // fused LSTM epilogue: stage 64 rows of gates at a time, then pointwise.
        // Reads h from A (buffer t&1), writes h to hout (buffer (t+1)&1) -> no
        // same-launch read/write race on the h matrix.
        const int cc2 = c * 2;
        const int rr = tid >> 2;
        const int jj0 = (tid & 3) * 8;
#pragma unroll
        for (int half = 0; half < 2; half++) {
            if (wm == half * 64) {
#pragma unroll
                for (int mt = 0; mt < 4; mt++) {
                    int lr0 = mt * 16 + r;
#pragma unroll
                    for (int nt = 0; nt < 4; nt++) {
                        int col = wn + nt * 8 + cc2;
                        gbuf[lr0 * 132 + col]           = acc[mt][nt][0];
                        gbuf[lr0 * 132 + col + 1]       = acc[mt][nt][1];
                        gbuf[(lr0 + 8) * 132 + col]     = acc[mt][nt][2];
                        gbuf[(lr0 + 8) * 132 + col + 1] = acc[mt][nt][3];
                    }
                }
            }
            __syncthreads();
            int row = m0 + half * 64 + rr;
            if (row < M) {
                int node = g_order[row];
                int idx  = nbr[(size_t)node * L + t];   // active rows => idx > 0
                const float* gx = (idx <= T_EDGES)
                    ? g_gxs + (size_t)(idx - 1) * NG
                    : g_gxo + (size_t)(idx - 1 - T_EDGES) * NG;
#pragma unroll
                for (int u = 0; u < 8; u++) {
                    int jj = jj0 + u;
                    float gi = gbuf[rr * 132 + jj]      + gx[n0 + jj]      + g_bias[n0 + jj];
                    float gf = gbuf[rr * 132 + 32 + jj] + gx[n0 + 32 + jj] + g_bias[n0 + 32 + jj];
                    float gg = gbuf[rr * 132 + 64 + jj] + gx[n0 + 64 + jj] + g_bias[n0 + 64 + jj];
                    float go = gbuf[rr * 132 + 96 + jj] + gx[n0 + 96 + jj] + g_bias[n0 + 96 + jj];
                    int j = (n0 >> 2) + jj;    // global hidden index
                    float cc = g_cs[(size_t)row * HH + j];
                    float c2 = sigm(gf) * cc + sigm(gi) * tanhf(gg);
                    float h2 = sigm(go) * tanhf(c2);
                    g_cs[(size_t)row * HH + j] = c2;
                    hout[(size_t)row * HH + j] = roundtf(h2);
                }
            }
            __syncthreads();
        }
    }
}

// ---------------- prep / pointwise kernels -------------------------------------
__global__ void k_round(const float* __restrict__ src, float* __restrict__ dst, int n)
{
    int i = blockIdx.x * blockDim.x + threadIdx.x;
    if (i < n) dst[i] = roundtf(src[i]);
}

// permute rows of W[2048,512] by gate interleave and round
__global__ void k_perm_w(const float* __restrict__ W, float* __restrict__ out)
{
    int i = blockIdx.x * blockDim.x + threadIdx.x;
    if (i >= 2048 * 512) return;
    int p = i >> 9, k = i & 511;
    int g = (p >> 5) & 3, tg = p >> 7, jj = p & 31;
    int orig = g * 512 + tg * 32 + jj;
    out[i] = roundtf(W[(size_t)orig * 512 + k]);
}

__global__ void k_perm_bias(const float* __restrict__ bih, const float* __restrict__ bhh)
{
    int p = blockIdx.x * blockDim.x + threadIdx.x;
    if (p >= 2048) return;
    int g = (p >> 5) & 3, tg = p >> 7, jj = p & 31;
    int orig = g * 512 + tg * 32 + jj;
    g_bias[p] = bih[orig] + bhh[orig];
}

__global__ void k_zero_hist()
{
    int i = blockIdx.x * blockDim.x + threadIdx.x;
    if (i < HIST_SZ) g_hist[i] = 0;
}
__global__ void k_hist(const int* __restrict__ lengths)
{
    int n = blockIdx.x * blockDim.x + threadIdx.x;
    if (n < O_NODES) atomicAdd(&g_hist[lengths[n]], 1);
}
__global__ void k_scan(int L)
{
    int run = 0;
    for (int len = L; len >= 0; --len) {
        g_cursor[len] = run;
        g_cnt[len]    = run;
        run += g_hist[len];
    }
}
__global__ void k_scatter(const int* __restrict__ lengths)
{
    int n = blockIdx.x * blockDim.x + threadIdx.x;
    if (n >= O_NODES) return;
    int pos = atomicAdd(&g_cursor[lengths[n]], 1);
    g_order[pos] = n;
    g_pos[n] = pos;
}

__global__ void k_build_cur(const float* __restrict__ obj,
                            const float* __restrict__ pred,
                            const int* __restrict__ edges)
{
    int i = blockIdx.x * blockDim.x + threadIdx.x;
    if (i >= T_EDGES * 384) return;
    int e = i / 384, q = i - e * 384;
    float v;
    if (q < 128)       v = obj[(size_t)edges[2 * e] * 128 + q];
    else if (q < 256)  v = pred[(size_t)e * 128 + (q - 128)];
    else               v = obj[(size_t)edges[2 * e + 1] * 128 + (q - 256)];
    g_cur[(size_t)e * 384 + q] = roundtf(v);
}

__global__ void k_copy_newp(float* __restrict__ out)
{
    int i = blockIdx.x * blockDim.x + threadIdx.x;
    if (i >= T_EDGES * 32) return;
    int e = i / 32, q = i - e * 32;
    ((float4*)out)[(size_t)(O_NODES * 32) + (size_t)e * 32 + q] =
        ((const float4*)g_newt)[(size_t)e * 288 + 128 + q];
}

// step 0: x=0, h=0 -> gates = biases only; identical for all nodes
__global__ void k_step0a()
{
    int j = threadIdx.x;
    int tg = j >> 5, jj = j & 31;
    int base = tg * 128 + jj;
    float gi = g_bias[base];
    float gf = g_bias[base + 32];
    float gg = g_bias[base + 64];
    float go = g_bias[base + 96];
    float c1 = sigm(gi) * tanhf(gg);          // c0 = 0
    float h1 = sigm(go) * tanhf(c1);
    g_c1[j] = c1;
    g_h1[j] = roundtf(h1);
}
// step 0 "writes" buffer 1 (read by step 1)
__global__ void k_step0b()
{
    int i = blockIdx.x * blockDim.x + threadIdx.x;
    if (i >= O_NODES * HH) return;
    g_cs[i]  = g_c1[i & 511];
    g_hsB[i] = g_h1[i & 511];
}

// pooled[n] = hbuf[lengths[n] & 1] at sorted row pos[n]; prev appended
__global__ void k_build_pc(const int* __restrict__ lengths)
{
    int i = blockIdx.x * blockDim.x + threadIdx.x;
    if (i >= O_NODES * 256) return;
    int n = i >> 8, q = i & 255;
    float4 v;
    if (q < 128) {
        const float* hb = (lengths[n] & 1) ? g_hsB : g_hsA;
        v = ((const float4*)hb)[(size_t)g_pos[n] * 128 + q];
    } else {
        v = ((const float4*)g_prev)[(size_t)n * 128 + (q - 128)];
    }
    ((float4*)g_pc)[(size_t)n * 256 + q] = v;
}

// ---------------- launcher -----------------------------------------------------
extern "C" void kernel_launch(void* const* d_in, const int* in_sizes, int n_in,
                              void* d_out, int out_size)
{
    const float* obj    = (const float*)d_in[0];
    const float* pred   = (const float*)d_in[1];
    const int*   edges  = (const int*)  d_in[2];
    const int*   nbr    = (const int*)  d_in[3];
    const int*   lengths= (const int*)  d_in[4];
    const float* W1     = (const float*)d_in[5];
    const float* b1     = (const float*)d_in[6];
    const float* W2     = (const float*)d_in[7];
    const float* b2     = (const float*)d_in[8];
    const float* Wih    = (const float*)d_in[9];
    const float* Whh    = (const float*)d_in[10];
    const float* bih    = (const float*)d_in[11];
    const float* bhh    = (const float*)d_in[12];
    const float* Wproj  = (const float*)d_in[13];
    const float* bproj  = (const float*)d_in[14];
    const float* Wout   = (const float*)d_in[15];
    const float* bout   = (const float*)d_in[16];
    float* out = (float*)d_out;

    const int L = in_sizes[3] / O_NODES;

    float *p_cur, *p_mid, *p_newt, *p_gxs, *p_gxo, *p_hsA, *p_hsB, *p_prev, *p_pc, *p_obj32;
    float *p_w1, *p_w2, *p_wih, *p_whh, *p_wproj, *p_wout;
    int *p_cnt;
    cudaGetSymbolAddress((void**)&p_cur,   g_cur);
    cudaGetSymbolAddress((void**)&p_mid,   g_mid);
    cudaGetSymbolAddress((void**)&p_newt,  g_newt);
    cudaGetSymbolAddress((void**)&p_gxs,   g_gxs);
    cudaGetSymbolAddress((void**)&p_gxo,   g_gxo);
    cudaGetSymbolAddress((void**)&p_hsA,   g_hsA);
    cudaGetSymbolAddress((void**)&p_hsB,   g_hsB);
    cudaGetSymbolAddress((void**)&p_prev,  g_prev);
    cudaGetSymbolAddress((void**)&p_pc,    g_pc);
    cudaGetSymbolAddress((void**)&p_obj32, g_obj32);
    cudaGetSymbolAddress((void**)&p_w1,    g_w1r);
    cudaGetSymbolAddress((void**)&p_w2,    g_w2r);
    cudaGetSymbolAddress((void**)&p_wih,   g_wihr);
    cudaGetSymbolAddress((void**)&p_whh,   g_whhr);
    cudaGetSymbolAddress((void**)&p_wproj, g_wprojr);
    cudaGetSymbolAddress((void**)&p_wout,  g_woutr);
    cudaGetSymbolAddress((void**)&p_cnt,   g_cnt);

    const int MT_E = (T_EDGES + 127) / 128;   // 391
    const int MT_O = (O_NODES + 127) / 128;   // 79

    // weight prep (round to tf32; Wih/Whh permuted)
    k_round<<<(512 * 384 + 255) / 256, 256>>>(W1, p_w1, 512 * 384);
    k_round<<<(1152 * 512 + 255) / 256, 256>>>(W2, p_w2, 1152 * 512);
    k_perm_w<<<(2048 * 512 + 255) / 256, 256>>>(Wih, p_wih);
    k_perm_w<<<(2048 * 512 + 255) / 256, 256>>>(Whh, p_whh);
    k_round<<<(512 * 128 + 255) / 256, 256>>>(Wproj, p_wproj, 512 * 128);
    k_round<<<(128 * 1024 + 255) / 256, 256>>>(Wout, p_wout, 128 * 1024);
    k_round<<<(O_NODES * 128 + 255) / 256, 256>>>(obj, p_obj32, O_NODES * 128);
    k_perm_bias<<<8, 256>>>(bih, bhh);

    // node sort by length (descending)
    k_zero_hist<<<HIST_SZ / 256, 256>>>();
    k_hist<<<(O_NODES + 255) / 256, 256>>>(lengths);
    k_scan<<<1, 1>>>(L);
    k_scatter<<<(O_NODES + 255) / 256, 256>>>(lengths);

    // edge MLP
    k_build_cur<<<(T_EDGES * 384 + 255) / 256, 256>>>(obj, pred, edges);
    tgemm<1, true ><<<dim3(4, MT_E), 256>>>(p_cur, 384, p_w1, 384, b1, p_mid, 512, T_EDGES, nullptr, 0, 0, nullptr, nullptr);
    tgemm<2, true ><<<dim3(9, MT_E), 256>>>(p_mid, 512, p_w2, 512, b2, p_newt, 1152, T_EDGES, nullptr, 0, 0, nullptr, nullptr);
    k_copy_newp<<<(T_EDGES * 32 + 255) / 256, 256>>>(out);

    // LSTM input-gate precompute (permuted gate columns)
    tgemm<0, false><<<dim3(16, MT_E), 256>>>(p_newt,       1152, p_wih, 512, nullptr, p_gxs, NG, T_EDGES, nullptr, 0, 0, nullptr, nullptr);
    tgemm<0, false><<<dim3(16, MT_E), 256>>>(p_newt + 640, 1152, p_wih, 512, nullptr, p_gxo, NG, T_EDGES, nullptr, 0, 0, nullptr, nullptr);

    // prev = obj @ Wproj^T + bproj
    tgemm<3, true ><<<dim3(4, MT_O), 256>>>(p_obj32, 128, p_wproj, 128, bproj, p_prev, 512, O_NODES, nullptr, 0, 0, nullptr, nullptr);

    // LSTM step 0 closed form (writes buffer B), then fused steps t=1..L-1:
    // step t reads hbuf[t&1], writes hbuf[(t+1)&1]  (ping-pong, no intra-launch race)
    k_step0a<<<1, 512>>>();
    k_step0b<<<(O_NODES * HH + 255) / 256, 256>>>();
    for (int t = 1; t < L; ++t) {
        float* hin  = (t & 1) ? p_hsB : p_hsA;
        float* hout = (t & 1) ? p_hsA : p_hsB;
        tgemm<4, false><<<dim3(16, MT_O), 256>>>(hin, 512, p_whh, 512, nullptr, nullptr, 0, O_NODES, p_cnt + t, t, L, nbr, hout);
    }

    // new_obj = [pooled | prev] @ Wout^T + bout (exact epilogue)
    k_build_pc<<<(O_NODES * 256 + 255) / 256, 256>>>(lengths);
    tgemm<0, true ><<<dim3(1, MT_O), 256>>>(p_pc, 1024, p_wout, 1024, bout, out, 128, O_NODES, nullptr, 0, 0, nullptr, nullptr);
}

// round 9
// speedup vs baseline: 1.4838x; 1.1750x over previous
#include <cuda_runtime.h>
#include <cstdint>
#include <math.h>

// Problem constants
#define O_NODES 10000
#define T_EDGES 50000
#define HH      512
#define NG      2048
#define HIST_SZ 131072

// ---------------- scratch (__device__ globals) --------------------------------
__device__ float g_cur [(size_t)T_EDGES * 384];
__device__ float g_mid [(size_t)T_EDGES * HH];
__device__ float g_newt[(size_t)T_EDGES * 1152];
__device__ float g_gxs [(size_t)T_EDGES * NG];
__device__ float g_gxo [(size_t)T_EDGES * NG];
__device__ float g_hsA [(size_t)O_NODES * HH];    // h ping-pong buffer 0 (tf32-rounded)
__device__ float g_hsB [(size_t)O_NODES * HH];    // h ping-pong buffer 1
__device__ float g_cs  [(size_t)O_NODES * HH];    // full fp32 c state
__device__ float g_prev[(size_t)O_NODES * HH];
__device__ float g_pc  [(size_t)O_NODES * 1024];
__device__ float g_obj32[(size_t)O_NODES * 128];
// tf32-rounded weights (Wih/Whh rows gate-permuted)
__device__ float g_w1r   [512  * 384];
__device__ float g_w2r   [1152 * 512];
__device__ float g_wihr  [2048 * 512];
__device__ float g_whhr  [2048 * 512];
__device__ float g_wprojr[512  * 128];
__device__ float g_woutr [128  * 1024];
__device__ float g_bias  [2048];                  // permuted bih+bhh
__device__ float g_h1[512];
__device__ float g_c1[512];
// sort scratch
__device__ int g_hist[HIST_SZ];
__device__ int g_cursor[HIST_SZ];
__device__ int g_cnt[HIST_SZ];
__device__ int g_order[O_NODES];
__device__ int g_pos[O_NODES];

// ---------------- helpers ------------------------------------------------------
__device__ __forceinline__ float roundtf(float x) {
    unsigned u;
    asm("cvt.rna.tf32.f32 %0, %1;" : "=r"(u) : "f"(x));
    return __uint_as_float(u);
}
__device__ __forceinline__ float sigm(float x) { return 1.f / (1.f + expf(-x)); }

__device__ __forceinline__ void mma_tf32(float* d, const unsigned* a, const unsigned* b) {
    asm volatile(
        "mma.sync.aligned.m16n8k8.row.col.f32.tf32.tf32.f32 "
        "{%0,%1,%2,%3}, {%4,%5,%6,%7}, {%8,%9}, {%0,%1,%2,%3};\n"
        : "+f"(d[0]), "+f"(d[1]), "+f"(d[2]), "+f"(d[3])
        : "r"(a[0]), "r"(a[1]), "r"(a[2]), "r"(a[3]), "r"(b[0]), "r"(b[1]));
}
__device__ __forceinline__ void cpa16(unsigned sdst, const float* gsrc, int src_bytes) {
    asm volatile("cp.async.cg.shared.global [%0], [%1], 16, %2;\n"
                 :: "r"(sdst), "l"(gsrc), "r"(src_bytes) : "memory");
}
__device__ __forceinline__ void cpa_commit() {
    asm volatile("cp.async.commit_group;\n" ::: "memory");
}
template<int N>
__device__ __forceinline__ void cpa_wait() {
    asm volatile("cp.async.wait_group %0;\n" :: "n"(N) : "memory");
}

// ---------------- tf32 tensor-core GEMM ----------------------------------------
// C[M,N] = epi(A[M,K] @ B[N,K]^T). Inputs pre-rounded to tf32.
// Block 128x128, 4 warps x (64x64), BK=32 per stage, 2-stage cp.async.
// Dynamic smem: 2 stages x (A 128x36 + B 128x36) floats = 73728 B -> 2 CTAs/SM.
// EPI: 0 exact(+bias) | 1 relu+round(+bias) | 2 relu, round except cols[512,640)
//      3 round(+bias) | 4 fused LSTM gate epilogue (writes hout, not C)
#define PITCH   36
#define ASTG    (128 * PITCH)          // floats per A stage
#define TG_SMEM (4 * ASTG * 4)         // bytes: 2 stages x (A+B)

template<int EPI, bool BIAS>
__global__ void __launch_bounds__(128, 2)
tgemm(const float* __restrict__ A, int lda,
      const float* __restrict__ B, int K,
      const float* __restrict__ bias,
      float* __restrict__ C, int ldc,
      int M, const int* __restrict__ mdev,
      int t, int L, const int* __restrict__ nbr,
      float* __restrict__ hout)
{
    if (mdev) M = *mdev;
    const int m0 = blockIdx.y * 128;
    if (m0 >= M) return;
    const int n0 = blockIdx.x * 128;

    extern __shared__ float smem[];
    // stage s: A at s*ASTG, B at 2*ASTG + s*ASTG
    const unsigned sbase = (unsigned)__cvta_generic_to_shared(smem);

    const int tid  = threadIdx.x;
    const int warp = tid >> 5, lane = tid & 31;
    const int r = lane >> 2, c = lane & 3;
    const int wm = (warp & 1) * 64;
    const int wn = (warp >> 1) * 64;

    float acc[4][8][4];
#pragma unroll
    for (int i = 0; i < 4; i++)
#pragma unroll
        for (int j = 0; j < 8; j++)
#pragma unroll
            for (int q = 0; q < 4; q++) acc[i][j][q] = 0.f;

    const int nk = K >> 5;

    // loader: q = tid + i*128 over 1024 float4 per array; row=q>>3, f4=q&7
    auto load_stage = [&](int it, int stg) {
        int k0 = it << 5;
#pragma unroll
        for (int i = 0; i < 8; i++) {
            int q = tid + i * 128;
            int row = q >> 3, f4 = q & 7;
            unsigned soff = (unsigned)((stg * ASTG + row * PITCH + f4 * 4) * 4);
            const float* ga = A + (size_t)(m0 + row) * lda + k0 + f4 * 4;
            cpa16(sbase + soff, ga, ((m0 + row) < M) ? 16 : 0);
            const float* gb = B + (size_t)(n0 + row) * K + k0 + f4 * 4;
            cpa16(sbase + (unsigned)(2 * ASTG * 4) + soff, gb, 16);
        }
        cpa_commit();
    };

    load_stage(0, 0);

    for (int it = 0; it < nk; ++it) {
        if (it + 1 < nk) { load_stage(it + 1, (it + 1) & 1); cpa_wait<1>(); }
        else             { cpa_wait<0>(); }
        __syncthreads();

        const float* As = smem + (it & 1) * ASTG;
        const float* Bs = smem + 2 * ASTG + (it & 1) * ASTG;
#pragma unroll
        for (int kk = 0; kk < 32; kk += 8) {
            unsigned ua[4][4], ub[8][2];
#pragma unroll
            for (int mt = 0; mt < 4; mt++) {
                int mb = wm + mt * 16 + r;
                ua[mt][0] = __float_as_uint(As[(mb    ) * PITCH + kk + c    ]);
                ua[mt][1] = __float_as_uint(As[(mb + 8) * PITCH + kk + c    ]);
                ua[mt][2] = __float_as_uint(As[(mb    ) * PITCH + kk + c + 4]);
                ua[mt][3] = __float_as_uint(As[(mb + 8) * PITCH + kk + c + 4]);
            }
#pragma unroll
            for (int nf = 0; nf < 8; nf++) {
                int nb = wn + nf * 8 + r;
                ub[nf][0] = __float_as_uint(Bs[nb * PITCH + kk + c    ]);
                ub[nf][1] = __float_as_uint(Bs[nb * PITCH + kk + c + 4]);
            }
#pragma unroll
            for (int mt = 0; mt < 4; mt++)
#pragma unroll
                for (int nf = 0; nf < 8; nf++)
                    mma_tf32(acc[mt][nf], ua[mt], ub[nf]);
        }
        __syncthreads();
    }

    if (EPI != 4) {
        const int cc2 = c * 2;
#pragma unroll
        for (int mt = 0; mt < 4; mt++) {
            int row0 = m0 + wm + mt * 16 + r;
#pragma unroll
            for (int nf = 0; nf < 8; nf++) {
                int col = n0 + wn + nf * 8 + cc2;
                float bx = 0.f, by = 0.f;
                if (BIAS) { bx = bias[col]; by = bias[col + 1]; }
#pragma unroll
                for (int h = 0; h < 2; h++) {
                    int row = row0 + h * 8;
                    if (row >= M) continue;
                    float vx = acc[mt][nf][h * 2 + 0] + bx;
                    float vy = acc[mt][nf][h * 2 + 1] + by;
                    if (EPI == 1 || EPI == 2) { vx = fmaxf(vx, 0.f); vy = fmaxf(vy, 0.f); }
                    if (EPI == 1 || EPI == 3) { vx = roundtf(vx); vy = roundtf(vy); }
                    if (EPI == 2) {
                        if (col < 512 || col >= 640)         vx = roundtf(vx);
                        if (col + 1 < 512 || col + 1 >= 640) vy = roundtf(vy);
                    }
                    *(float2*)(C + (size_t)row * ldc + col) = make_float2(vx, vy);
                }
            }
        }
    } else {
        // fused LSTM epilogue: stage full 128x128 gate tile in smem (pipeline
        // buffers are dead), then pointwise. Reads h from A (buf t&1), writes
        // hout (buf (t+1)&1): no same-launch race.
        float* gbuf = smem;   // 128 x 132 floats = 67584 <= 73728
        const int cc2 = c * 2;
#pragma unroll
        for (int mt = 0; mt < 4; mt++) {
            int lr0 = wm + mt * 16 + r;
#pragma unroll
            for (int nf = 0; nf < 8; nf++) {
                int col = wn + nf * 8 + cc2;
                gbuf[lr0 * 132 + col]           = acc[mt][nf][0];
                gbuf[lr0 * 132 + col + 1]       = acc[mt][nf][1];
                gbuf[(lr0 + 8) * 132 + col]     = acc[mt][nf][2];
                gbuf[(lr0 + 8) * 132 + col + 1] = acc[mt][nf][3];
            }
        }
        __syncthreads();
        const int jj0 = (tid & 3) * 8;
#pragma unroll
        for (int pass = 0; pass < 4; pass++) {
            int rl = pass * 32 + (tid >> 2);
            int row = m0 + rl;
            if (row < M) {
                int node = g_order[row];
                int idx  = nbr[(size_t)node * L + t];   // active rows => idx > 0
                const float* gx = (idx <= T_EDGES)
                    ? g_gxs + (size_t)(idx - 1) * NG
                    : g_gxo + (size_t)(idx - 1 - T_EDGES) * NG;
#pragma unroll
                for (int u = 0; u < 8; u++) {
                    int jj = jj0 + u;
                    float gi = gbuf[rl * 132 + jj]      + gx[n0 + jj]      + g_bias[n0 + jj];
                    float gf = gbuf[rl * 132 + 32 + jj] + gx[n0 + 32 + jj] + g_bias[n0 + 32 + jj];
                    float gg = gbuf[rl * 132 + 64 + jj] + gx[n0 + 64 + jj] + g_bias[n0 + 64 + jj];
                    float go = gbuf[rl * 132 + 96 + jj] + gx[n0 + 96 + jj] + g_bias[n0 + 96 + jj];
                    int j = (n0 >> 2) + jj;    // global hidden index
                    float cc = g_cs[(size_t)row * HH + j];
                    float c2 = sigm(gf) * cc + sigm(gi) * tanhf(gg);
                    float h2 = sigm(go) * tanhf(c2);
                    g_cs[(size_t)row * HH + j] = c2;
                    hout[(size_t)row * HH + j] = roundtf(h2);
                }
            }
        }
    }
}

// ---------------- prep / pointwise kernels -------------------------------------
__global__ void k_round(const float* __restrict__ src, float* __restrict__ dst, int n)
{
    int i = blockIdx.x * blockDim.x + threadIdx.x;
    if (i < n) dst[i] = roundtf(src[i]);
}

// permute rows of W[2048,512] by gate interleave and round
__global__ void k_perm_w(const float* __restrict__ W, float* __restrict__ out)
{
    int i = blockIdx.x * blockDim.x + threadIdx.x;
    if (i >= 2048 * 512) return;
    int p = i >> 9, k = i & 511;
    int g = (p >> 5) & 3, tg = p >> 7, jj = p & 31;
    int orig = g * 512 + tg * 32 + jj;
    out[i] = roundtf(W[(size_t)orig * 512 + k]);
}

__global__ void k_perm_bias(const float* __restrict__ bih, const float* __restrict__ bhh)
{
    int p = blockIdx.x * blockDim.x + threadIdx.x;
    if (p >= 2048) return;
    int g = (p >> 5) & 3, tg = p >> 7, jj = p & 31;
    int orig = g * 512 + tg * 32 + jj;
    g_bias[p] = bih[orig] + bhh[orig];
}

__global__ void k_zero_hist()
{
    int i = blockIdx.x * blockDim.x + threadIdx.x;
    if (i < HIST_SZ) g_hist[i] = 0;
}
__global__ void k_hist(const int* __restrict__ lengths)
{
    int n = blockIdx.x * blockDim.x + threadIdx.x;
    if (n < O_NODES) atomicAdd(&g_hist[lengths[n]], 1);
}
__global__ void k_scan(int L)
{
    int run = 0;
    for (int len = L; len >= 0; --len) {
        g_cursor[len] = run;
        g_cnt[len]    = run;
        run += g_hist[len];
    }
}
__global__ void k_scatter(const int* __restrict__ lengths)
{
    int n = blockIdx.x * blockDim.x + threadIdx.x;
    if (n >= O_NODES) return;
    int pos = atomicAdd(&g_cursor[lengths[n]], 1);
    g_order[pos] = n;
    g_pos[n] = pos;
}

__global__ void k_build_cur(const float* __restrict__ obj,
                            const float* __restrict__ pred,
                            const int* __restrict__ edges)
{
    int i = blockIdx.x * blockDim.x + threadIdx.x;
    if (i >= T_EDGES * 384) return;
    int e = i / 384, q = i - e * 384;
    float v;
    if (q < 128)       v = obj[(size_t)edges[2 * e] * 128 + q];
    else if (q < 256)  v = pred[(size_t)e * 128 + (q - 128)];
    else               v = obj[(size_t)edges[2 * e + 1] * 128 + (q - 256)];
    g_cur[(size_t)e * 384 + q] = roundtf(v);
}

__global__ void k_copy_newp(float* __restrict__ out)
{
    int i = blockIdx.x * blockDim.x + threadIdx.x;
    if (i >= T_EDGES * 32) return;
    int e = i / 32, q = i - e * 32;
    ((float4*)out)[(size_t)(O_NODES * 32) + (size_t)e * 32 + q] =
        ((const float4*)g_newt)[(size_t)e * 288 + 128 + q];
}

// step 0: x=0, h=0 -> gates = biases only; identical for all nodes
__global__ void k_step0a()
{
    int j = threadIdx.x;
    int tg = j >> 5, jj = j & 31;
    int base = tg * 128 + jj;
    float gi = g_bias[base];
    float gf = g_bias[base + 32];
    float gg = g_bias[base + 64];
    float go = g_bias[base + 96];
    float c1 = sigm(gi) * tanhf(gg);          // c0 = 0
    float h1 = sigm(go) * tanhf(c1);
    g_c1[j] = c1;
    g_h1[j] = roundtf(h1);
}
// step 0 "writes" buffer 1 (read by step 1)
__global__ void k_step0b()
{
    int i = blockIdx.x * blockDim.x + threadIdx.x;
    if (i >= O_NODES * HH) return;
    g_cs[i]  = g_c1[i & 511];
    g_hsB[i] = g_h1[i & 511];
}

// pooled[n] = hbuf[lengths[n] & 1] at sorted row pos[n]; prev appended
__global__ void k_build_pc(const int* __restrict__ lengths)
{
    int i = blockIdx.x * blockDim.x + threadIdx.x;
    if (i >= O_NODES * 256) return;
    int n = i >> 8, q = i & 255;
    float4 v;
    if (q < 128) {
        const float* hb = (lengths[n] & 1) ? g_hsB : g_hsA;
        v = ((const float4*)hb)[(size_t)g_pos[n] * 128 + q];
    } else {
        v = ((const float4*)g_prev)[(size_t)n * 128 + (q - 128)];
    }
    ((float4*)g_pc)[(size_t)n * 256 + q] = v;
}

// ---------------- launcher -----------------------------------------------------
extern "C" void kernel_launch(void* const* d_in, const int* in_sizes, int n_in,
                              void* d_out, int out_size)
{
    const float* obj    = (const float*)d_in[0];
    const float* pred   = (const float*)d_in[1];
    const int*   edges  = (const int*)  d_in[2];
    const int*   nbr    = (const int*)  d_in[3];
    const int*   lengths= (const int*)  d_in[4];
    const float* W1     = (const float*)d_in[5];
    const float* b1     = (const float*)d_in[6];
    const float* W2     = (const float*)d_in[7];
    const float* b2     = (const float*)d_in[8];
    const float* Wih    = (const float*)d_in[9];
    const float* Whh    = (const float*)d_in[10];
    const float* bih    = (const float*)d_in[11];
    const float* bhh    = (const float*)d_in[12];
    const float* Wproj  = (const float*)d_in[13];
    const float* bproj  = (const float*)d_in[14];
    const float* Wout   = (const float*)d_in[15];
    const float* bout   = (const float*)d_in[16];
    float* out = (float*)d_out;

    const int L = in_sizes[3] / O_NODES;

    float *p_cur, *p_mid, *p_newt, *p_gxs, *p_gxo, *p_hsA, *p_hsB, *p_prev, *p_pc, *p_obj32;
    float *p_w1, *p_w2, *p_wih, *p_whh, *p_wproj, *p_wout;
    int *p_cnt;
    cudaGetSymbolAddress((void**)&p_cur,   g_cur);
    cudaGetSymbolAddress((void**)&p_mid,   g_mid);
    cudaGetSymbolAddress((void**)&p_newt,  g_newt);
    cudaGetSymbolAddress((void**)&p_gxs,   g_gxs);
    cudaGetSymbolAddress((void**)&p_gxo,   g_gxo);
    cudaGetSymbolAddress((void**)&p_hsA,   g_hsA);
    cudaGetSymbolAddress((void**)&p_hsB,   g_hsB);
    cudaGetSymbolAddress((void**)&p_prev,  g_prev);
    cudaGetSymbolAddress((void**)&p_pc,    g_pc);
    cudaGetSymbolAddress((void**)&p_obj32, g_obj32);
    cudaGetSymbolAddress((void**)&p_w1,    g_w1r);
    cudaGetSymbolAddress((void**)&p_w2,    g_w2r);
    cudaGetSymbolAddress((void**)&p_wih,   g_wihr);
    cudaGetSymbolAddress((void**)&p_whh,   g_whhr);
    cudaGetSymbolAddress((void**)&p_wproj, g_wprojr);
    cudaGetSymbolAddress((void**)&p_wout,  g_woutr);
    cudaGetSymbolAddress((void**)&p_cnt,   g_cnt);

    cudaFuncSetAttribute(tgemm<0, false>, cudaFuncAttributeMaxDynamicSharedMemorySize, TG_SMEM);
    cudaFuncSetAttribute(tgemm<0, true >, cudaFuncAttributeMaxDynamicSharedMemorySize, TG_SMEM);
    cudaFuncSetAttribute(tgemm<1, true >, cudaFuncAttributeMaxDynamicSharedMemorySize, TG_SMEM);
    cudaFuncSetAttribute(tgemm<2, true >, cudaFuncAttributeMaxDynamicSharedMemorySize, TG_SMEM);
    cudaFuncSetAttribute(tgemm<3, true >, cudaFuncAttributeMaxDynamicSharedMemorySize, TG_SMEM);
    cudaFuncSetAttribute(tgemm<4, false>, cudaFuncAttributeMaxDynamicSharedMemorySize, TG_SMEM);

    const int MT_E = (T_EDGES + 127) / 128;   // 391
    const int MT_O = (O_NODES + 127) / 128;   // 79

    // weight prep (round to tf32; Wih/Whh permuted)
    k_round<<<(512 * 384 + 255) / 256, 256>>>(W1, p_w1, 512 * 384);
    k_round<<<(1152 * 512 + 255) / 256, 256>>>(W2, p_w2, 1152 * 512);
    k_perm_w<<<(2048 * 512 + 255) / 256, 256>>>(Wih, p_wih);
    k_perm_w<<<(2048 * 512 + 255) / 256, 256>>>(Whh, p_whh);
    k_round<<<(512 * 128 + 255) / 256, 256>>>(Wproj, p_wproj, 512 * 128);
    k_round<<<(128 * 1024 + 255) / 256, 256>>>(Wout, p_wout, 128 * 1024);
    k_round<<<(O_NODES * 128 + 255) / 256, 256>>>(obj, p_obj32, O_NODES * 128);
    k_perm_bias<<<8, 256>>>(bih, bhh);

    // node sort by length (descending)
    k_zero_hist<<<HIST_SZ / 256, 256>>>();
    k_hist<<<(O_NODES + 255) / 256, 256>>>(lengths);
    k_scan<<<1, 1>>>(L);
    k_scatter<<<(O_NODES + 255) / 256, 256>>>(lengths);

    // edge MLP
    k_build_cur<<<(T_EDGES * 384 + 255) / 256, 256>>>(obj, pred, edges);
    tgemm<1, true ><<<dim3(4, MT_E), 128, TG_SMEM>>>(p_cur, 384, p_w1, 384, b1, p_mid, 512, T_EDGES, nullptr, 0, 0, nullptr, nullptr);
    tgemm<2, true ><<<dim3(9, MT_E), 128, TG_SMEM>>>(p_mid, 512, p_w2, 512, b2, p_newt, 1152, T_EDGES, nullptr, 0, 0, nullptr, nullptr);
    k_copy_newp<<<(T_EDGES * 32 + 255) / 256, 256>>>(out);

    // LSTM input-gate precompute (permuted gate columns)
    tgemm<0, false><<<dim3(16, MT_E), 128, TG_SMEM>>>(p_newt,       1152, p_wih, 512, nullptr, p_gxs, NG, T_EDGES, nullptr, 0, 0, nullptr, nullptr);
    tgemm<0, false><<<dim3(16, MT_E), 128, TG_SMEM>>>(p_newt + 640, 1152, p_wih, 512, nullptr, p_gxo, NG, T_EDGES, nullptr, 0, 0, nullptr, nullptr);

    // prev = obj @ Wproj^T + bproj
    tgemm<3, true ><<<dim3(4, MT_O), 128, TG_SMEM>>>(p_obj32, 128, p_wproj, 128, bproj, p_prev, 512, O_NODES, nullptr, 0, 0, nullptr, nullptr);

    // LSTM step 0 closed form (writes buffer B), then fused steps t=1..L-1:
    // step t reads hbuf[t&1], writes hbuf[(t+1)&1]  (ping-pong, no intra-launch race)
    k_step0a<<<1, 512>>>();
    k_step0b<<<(O_NODES * HH + 255) / 256, 256>>>();
    for (int t = 1; t < L; ++t) {
        float* hin  = (t & 1) ? p_hsB : p_hsA;
        float* hout = (t & 1) ? p_hsA : p_hsB;
        tgemm<4, false><<<dim3(16, MT_O), 128, TG_SMEM>>>(hin, 512, p_whh, 512, nullptr, nullptr, 0, O_NODES, p_cnt + t, t, L, nbr, hout);
    }

    // new_obj = [pooled | prev] @ Wout^T + bout (exact epilogue)
    k_build_pc<<<(O_NODES * 256 + 255) / 256, 256>>>(lengths);
    tgemm<0, true ><<<dim3(1, MT_O), 128, TG_SMEM>>>(p_pc, 1024, p_wout, 1024, bout, out, 128, O_NODES, nullptr, 0, 0, nullptr, nullptr);
}